// round 11
// baseline (speedup 1.0000x reference)
#include <cuda_runtime.h>
#include <cuda_bf16.h>
#include <cstdint>

// HardNetLoss, screen-then-fix v5:
//   int8 screening GEMM dumping S~ as int8 + per-tile row/col maxes,
//   hierarchical scan with STREAMING exact fix (ballot-iterate, no candidate
//   list, no overflow possible), exact diagonal, tiny finish.

#define CNT 8192
#define KDIM 256
#define EPSV 1e-6f
#define MARGIN_C 0.08f

#define TSTRIDE 272
#define TILE_BYTES (128 * TSTRIDE)        // 34816
#define SSTRIDE 144                       // int8 stage stride (16B aligned)
#define SM_SROW (2 * TILE_BYTES)
#define SM_SCOL (2 * TILE_BYTES + 512)
#define SM_TOTAL (2 * TILE_BYTES + 1024)  // 70656

#define NT 64                             // tiles per dimension

__device__ unsigned char g_q[2 * CNT * KDIM];
__device__ unsigned char g_S8[(size_t)CNT * CNT];   // 64 MiB screened S~ (int8, s*127)
__device__ float g_trow[(size_t)CNT * NT];          // per-tile row max (excl diag)
__device__ float g_tcol[(size_t)CNT * NT];          // per-tile col max (excl diag)
__device__ float g_erow[CNT], g_ecol[CNT];          // exact maxes
__device__ float g_diag[CNT];
__device__ float g_partial[CNT / 256];
__device__ unsigned g_maxabs;

__device__ __forceinline__ unsigned encf(float f) {
    unsigned u = __float_as_uint(f);
    return (u & 0x80000000u) ? ~u : (u | 0x80000000u);
}
__device__ __forceinline__ float decf(unsigned e) {
    unsigned u = (e & 0x80000000u) ? (e & 0x7fffffffu) : ~e;
    return __uint_as_float(u);
}
__device__ __forceinline__ uint32_t smem_u32(const void* p) {
    uint32_t a;
    asm("{ .reg .u64 t; cvta.to.shared.u64 t, %1; cvt.u32.u64 %0, t; }" : "=r"(a) : "l"(p));
    return a;
}
__device__ __forceinline__ void cp_async16(uint32_t saddr, const void* gaddr) {
    asm volatile("cp.async.cg.shared.global [%0], [%1], 16;" :: "r"(saddr), "l"(gaddr) : "memory");
}
__device__ __forceinline__ void mma_s8(int* c, const uint32_t* a, const uint32_t* b) {
    asm volatile(
        "mma.sync.aligned.m16n8k32.row.col.s32.s8.s8.s32 "
        "{%0,%1,%2,%3}, {%4,%5,%6,%7}, {%8,%9}, {%0,%1,%2,%3};"
        : "+r"(c[0]), "+r"(c[1]), "+r"(c[2]), "+r"(c[3])
        : "r"(a[0]), "r"(a[1]), "r"(a[2]), "r"(a[3]), "r"(b[0]), "r"(b[1]));
}
__device__ __forceinline__ float qscale() {
    return 126.5f / __uint_as_float(g_maxabs);
}

// warp-collective exact dot: s = <x[ar], x[CNT+pr]>
__device__ __forceinline__ float exact_dot(const float* __restrict__ x,
                                           int ar, int pr, int lane) {
    const float4* ap = reinterpret_cast<const float4*>(x + (size_t)ar * KDIM);
    const float4* pp = reinterpret_cast<const float4*>(x + (size_t)(CNT + pr) * KDIM);
    float sum = 0.0f;
#pragma unroll
    for (int t = 0; t < 2; t++) {
        float4 a = ap[lane * 2 + t], p = pp[lane * 2 + t];
        sum += a.x * p.x + a.y * p.y + a.z * p.z + a.w * p.w;
    }
#pragma unroll
    for (int st = 16; st; st >>= 1) sum += __shfl_xor_sync(~0u, sum, st);
    return sum;
}

// ---------------- prep ----------------
__global__ void maxabs_kernel(const float* __restrict__ x) {
    __shared__ float red[8];
    const float4* X4 = reinterpret_cast<const float4*>(x);
    int i = blockIdx.x * 256 + threadIdx.x;
    float m = 0.0f;
#pragma unroll
    for (int t = 0; t < 4; t++) {
        float4 v = X4[i + t * 262144];
        m = fmaxf(m, fmaxf(fmaxf(fabsf(v.x), fabsf(v.y)), fmaxf(fabsf(v.z), fabsf(v.w))));
    }
#pragma unroll
    for (int st = 16; st; st >>= 1) m = fmaxf(m, __shfl_xor_sync(~0u, m, st));
    if ((threadIdx.x & 31) == 0) red[threadIdx.x >> 5] = m;
    __syncthreads();
    if (threadIdx.x < 8) {
        m = red[threadIdx.x];
#pragma unroll
        for (int st = 4; st; st >>= 1) m = fmaxf(m, __shfl_xor_sync(0xffu, m, st));
        if (threadIdx.x == 0) atomicMax(&g_maxabs, __float_as_uint(m));
    }
}

__global__ void quant_kernel(const float* __restrict__ x) {
    int i = blockIdx.x * 256 + threadIdx.x;
    float sc = qscale();
    float4 v = reinterpret_cast<const float4*>(x)[i];
    float q[4] = {v.x, v.y, v.z, v.w};
    uint32_t w = 0;
#pragma unroll
    for (int j = 0; j < 4; j++)
        w |= ((uint32_t)((int)rintf(q[j] * sc) & 0xff)) << (8 * j);
    reinterpret_cast<uint32_t*>(g_q)[i] = w;
}

// ---------------- screening GEMM ----------------
__global__ __launch_bounds__(256, 2)
void gemm_screen() {
    extern __shared__ char smem[];
    const uint32_t sb = smem_u32(smem);
    const int tid = threadIdx.x;
    const int w = tid >> 5, l = tid & 31;
    const int wm = w >> 2, wn = w & 3;
    const int bx = blockIdx.x, by = blockIdx.y;

    const char* Ag = (const char*)g_q + (size_t)(by * 128) * KDIM;
    const char* Bg = (const char*)g_q + (size_t)(CNT + bx * 128) * KDIM;

#pragma unroll
    for (int i = 0; i < 8; i++) {
        int idx = tid + i * 256;
        int row = idx >> 4, c16 = idx & 15;
        uint32_t so = (uint32_t)row * TSTRIDE + c16 * 16;
        cp_async16(sb + so, Ag + row * KDIM + c16 * 16);
        cp_async16(sb + TILE_BYTES + so, Bg + row * KDIM + c16 * 16);
    }
    asm volatile("cp.async.commit_group;" ::: "memory");
    asm volatile("cp.async.wait_group 0;" ::: "memory");
    __syncthreads();

    int acc[16][4];
#pragma unroll
    for (int t = 0; t < 16; t++)
#pragma unroll
        for (int e = 0; e < 4; e++) acc[t][e] = 0;

#pragma unroll
    for (int k0 = 0; k0 < KDIM; k0 += 32) {
        uint32_t a[4][4], b[4][2];
#pragma unroll
        for (int mt = 0; mt < 4; mt++) {
            const char* p = smem + (uint32_t)(wm * 64 + mt * 16 + (l >> 2)) * TSTRIDE
                          + k0 + (l & 3) * 4;
            a[mt][0] = *reinterpret_cast<const uint32_t*>(p);
            a[mt][1] = *reinterpret_cast<const uint32_t*>(p + 8 * TSTRIDE);
            a[mt][2] = *reinterpret_cast<const uint32_t*>(p + 16);
            a[mt][3] = *reinterpret_cast<const uint32_t*>(p + 8 * TSTRIDE + 16);
        }
#pragma unroll
        for (int nt = 0; nt < 4; nt++) {
            const char* p = smem + TILE_BYTES + (uint32_t)(wn * 32 + nt * 8 + (l >> 2)) * TSTRIDE
                          + k0 + (l & 3) * 4;
            b[nt][0] = *reinterpret_cast<const uint32_t*>(p);
            b[nt][1] = *reinterpret_cast<const uint32_t*>(p + 16);
        }
#pragma unroll
        for (int mt = 0; mt < 4; mt++)
#pragma unroll
            for (int nt = 0; nt < 4; nt++)
                mma_s8(acc[mt * 4 + nt], a[mt], b[nt]);
    }

    // ---- epilogue: maxes in regs, stage int8 tile, coalesced dump + tile maxes ----
    unsigned* srow = reinterpret_cast<unsigned*>(smem + SM_SROW);
    unsigned* scol = reinterpret_cast<unsigned*>(smem + SM_SCOL);
    const float inv2 = 1.0f / (qscale() * qscale());

    float rmax[8], cmax[8];
#pragma unroll
    for (int i = 0; i < 8; i++) { rmax[i] = -2.0f; cmax[i] = -2.0f; }

    __syncthreads();               // done reading A/B tiles
    if (tid < 128) srow[tid] = 0u; else scol[tid - 128] = 0u;
    __syncthreads();

#pragma unroll
    for (int mt = 0; mt < 4; mt++)
#pragma unroll
        for (int nt = 0; nt < 4; nt++)
#pragma unroll
            for (int h = 0; h < 2; h++) {
                int lr = wm * 64 + mt * 16 + (l >> 2) + h * 8;
                int lc = wn * 32 + nt * 8 + 2 * (l & 3);
                float s0 = (float)acc[mt * 4 + nt][2 * h + 0] * inv2;
                float s1 = (float)acc[mt * 4 + nt][2 * h + 1] * inv2;
                int i0 = (int)rintf(fminf(fmaxf(s0 * 127.0f, -127.0f), 127.0f));
                int i1 = (int)rintf(fminf(fmaxf(s1 * 127.0f, -127.0f), 127.0f));
                unsigned short pk = (unsigned short)((i0 & 0xff) | ((i1 & 0xff) << 8));
                *reinterpret_cast<unsigned short*>(smem + (uint32_t)lr * SSTRIDE + lc) = pk;
                if (by * 128 + lr == bx * 128 + lc) s0 = -2.0f;
                if (by * 128 + lr == bx * 128 + lc + 1) s1 = -2.0f;
                rmax[mt * 2 + h] = fmaxf(rmax[mt * 2 + h], fmaxf(s0, s1));
                cmax[nt * 2 + 0] = fmaxf(cmax[nt * 2 + 0], s0);
                cmax[nt * 2 + 1] = fmaxf(cmax[nt * 2 + 1], s1);
            }

#pragma unroll
    for (int st = 1; st <= 2; st <<= 1)
#pragma unroll
        for (int i = 0; i < 8; i++)
            rmax[i] = fmaxf(rmax[i], __shfl_xor_sync(0xffffffffu, rmax[i], st));
    if ((l & 3) == 0) {
#pragma unroll
        for (int mt = 0; mt < 4; mt++)
#pragma unroll
            for (int h = 0; h < 2; h++)
                atomicMax(&srow[wm * 64 + mt * 16 + (l >> 2) + h * 8], encf(rmax[mt * 2 + h]));
    }
#pragma unroll
    for (int st = 4; st <= 16; st <<= 1)
#pragma unroll
        for (int i = 0; i < 8; i++)
            cmax[i] = fmaxf(cmax[i], __shfl_xor_sync(0xffffffffu, cmax[i], st));
    if (l < 4) {
#pragma unroll
        for (int nt = 0; nt < 4; nt++)
#pragma unroll
            for (int j = 0; j < 2; j++)
                atomicMax(&scol[wn * 32 + nt * 8 + 2 * l + j], encf(cmax[nt * 2 + j]));
    }
    __syncthreads();

    // coalesced 16B dump of staged int8 tile + tile max writes
#pragma unroll
    for (int i = 0; i < 4; i++) {
        int idx = tid + i * 256;
        int row = idx >> 3, c16 = idx & 7;
        uint4 v = *reinterpret_cast<const uint4*>(smem + (uint32_t)row * SSTRIDE + c16 * 16);
        *reinterpret_cast<uint4*>(g_S8 + (size_t)(by * 128 + row) * CNT + bx * 128 + c16 * 16) = v;
    }
    if (tid < 128) g_trow[(size_t)(by * 128 + tid) * NT + bx] = decf(srow[tid]);
    else           g_tcol[(size_t)(bx * 128 + tid - 128) * NT + by] = decf(scol[tid - 128]);
}

// ---------------- hierarchical scan, streaming exact fix (no lists) ----------------
__global__ __launch_bounds__(256)
void scan3(const float* __restrict__ x) {
    const int warp = threadIdx.x >> 5, lane = threadIdx.x & 31;
    const int r = blockIdx.x * 8 + warp;       // row (dir 0) or col (dir 1)
    const int dir = blockIdx.y;

    const float* tmax = dir ? g_tcol : g_trow;
    float v0 = tmax[(size_t)r * NT + lane];
    float v1 = tmax[(size_t)r * NT + 32 + lane];
    float m = fmaxf(v0, v1);
#pragma unroll
    for (int st = 16; st; st >>= 1) m = fmaxf(m, __shfl_xor_sync(~0u, m, st));
    const float thr = m - MARGIN_C;

    unsigned ball[2];
    ball[0] = __ballot_sync(~0u, v0 >= thr);
    ball[1] = __ballot_sync(~0u, v1 >= thr);

    const float dec = 1.0f / 127.0f;
    float best = -2.0f;

#pragma unroll
    for (int half = 0; half < 2; half++) {
        unsigned act = ball[half];
        while (act) {
            int t = (__ffs(act) - 1) + half * 32;
            act &= act - 1;
            // load this lane's 4 bytes of the segment
            uint32_t wv;
            if (dir == 0) {
                wv = *reinterpret_cast<const uint32_t*>(
                    g_S8 + (size_t)r * CNT + t * 128 + lane * 4);
            } else {
                int ib = t * 128 + lane * 4;
                wv = (uint32_t)g_S8[(size_t)(ib + 0) * CNT + r]
                   | ((uint32_t)g_S8[(size_t)(ib + 1) * CNT + r] << 8)
                   | ((uint32_t)g_S8[(size_t)(ib + 2) * CNT + r] << 16)
                   | ((uint32_t)g_S8[(size_t)(ib + 3) * CNT + r] << 24);
            }
#pragma unroll
            for (int k = 0; k < 4; k++) {
                float s = (float)((int)(char)(wv >> (8 * k))) * dec;
                int idx = t * 128 + lane * 4 + k;
                bool cand = (s >= thr) && (idx != r);
                unsigned bal = __ballot_sync(~0u, cand);
                while (bal) {
                    int src = __ffs(bal) - 1;
                    bal &= bal - 1;
                    int j = t * 128 + src * 4 + k;
                    float sum = (dir == 0) ? exact_dot(x, r, j, lane)
                                           : exact_dot(x, j, r, lane);
                    best = fmaxf(best, sum);
                }
            }
        }
    }
    if (lane == 0) {
        if (dir == 0) g_erow[r] = best;
        else          g_ecol[r] = best;
    }
}

__global__ void diag_kernel(const float* __restrict__ x) {
    int gw = (blockIdx.x * blockDim.x + threadIdx.x) >> 5;
    int lane = threadIdx.x & 31;
    float sum = exact_dot(x, gw, gw, lane);
    if (lane == 0) g_diag[gw] = sum;
}

__global__ void finish_kernel() {
    __shared__ float red[256];
    int i = blockIdx.x * 256 + threadIdx.x;
    float smax = fmaxf(g_erow[i], g_ecol[i]);
    float neg = sqrtf((1.0f - smax + EPSV) * 2.0f);
    float pos = sqrtf((1.0f - g_diag[i] + EPSV) * 2.0f);
    float t = fmaxf(1.0f - neg + pos, 0.0f);
    red[threadIdx.x] = t;
    __syncthreads();
#pragma unroll
    for (int s = 128; s > 0; s >>= 1) {
        if (threadIdx.x < s) red[threadIdx.x] += red[threadIdx.x + s];
        __syncthreads();
    }
    if (threadIdx.x == 0) g_partial[blockIdx.x] = red[0];
}

__global__ void final_kernel(float* __restrict__ out) {
    if (threadIdx.x == 0) {
        float s = 0.0f;
        for (int i = 0; i < CNT / 256; i++) s += g_partial[i];
        out[0] = s / (float)CNT;
    }
}

extern "C" void kernel_launch(void* const* d_in, const int* in_sizes, int n_in,
                              void* d_out, int out_size) {
    (void)in_sizes; (void)n_in; (void)out_size;
    const float* x = (const float*)d_in[0];
    float* out = (float*)d_out;

    cudaFuncSetAttribute((const void*)gemm_screen,
                         cudaFuncAttributeMaxDynamicSharedMemorySize, SM_TOTAL);

    maxabs_kernel<<<1024, 256>>>(x);
    quant_kernel<<<2 * CNT * KDIM / 4 / 256, 256>>>(x);
    dim3 grid(CNT / 128, CNT / 128);
    gemm_screen<<<grid, 256, SM_TOTAL>>>();
    dim3 sgrid(CNT / 8, 2);
    scan3<<<sgrid, 256>>>(x);
    diag_kernel<<<CNT * 32 / 256, 256>>>(x);
    finish_kernel<<<CNT / 256, 256>>>();
    final_kernel<<<1, 32>>>(out);
}

// round 12
// speedup vs baseline: 8.2096x; 8.2096x over previous
#include <cuda_runtime.h>
#include <cuda_bf16.h>
#include <cstdint>

// HardNetLoss, screen-then-fix v6:
//   int8 screening GEMM -> per-8-element group maxes only (no S~ dump),
//   scan: warp/row reads 1024 group maxes, exact fp32 dots on rare passing
//   groups (streaming, no lists), diag fused. Exact result.

#define CNT 8192
#define KDIM 256
#define EPSV 1e-6f
#define MARGIN_C 0.05f

#define TSTRIDE 272
#define TILE_BYTES (128 * TSTRIDE)        // 34816
#define SM_TOTAL (2 * TILE_BYTES + 1024)  // 70656

__device__ unsigned char g_q[2 * CNT * KDIM];
__device__ __nv_bfloat16 g_grow[(size_t)CNT * 1024];   // row-dir group maxes (16MB)
__device__ __nv_bfloat16 g_gcol[(size_t)CNT * 1024];   // col-dir group maxes (16MB)
__device__ float g_erow[CNT], g_ecol[CNT];
__device__ float g_diag[CNT];
__device__ float g_partial[CNT / 256];
__device__ unsigned g_maxabs;

__device__ __forceinline__ uint32_t smem_u32(const void* p) {
    uint32_t a;
    asm("{ .reg .u64 t; cvta.to.shared.u64 t, %1; cvt.u32.u64 %0, t; }" : "=r"(a) : "l"(p));
    return a;
}
__device__ __forceinline__ void cp_async16(uint32_t saddr, const void* gaddr) {
    asm volatile("cp.async.cg.shared.global [%0], [%1], 16;" :: "r"(saddr), "l"(gaddr) : "memory");
}
__device__ __forceinline__ void mma_s8(int* c, const uint32_t* a, const uint32_t* b) {
    asm volatile(
        "mma.sync.aligned.m16n8k32.row.col.s32.s8.s8.s32 "
        "{%0,%1,%2,%3}, {%4,%5,%6,%7}, {%8,%9}, {%0,%1,%2,%3};"
        : "+r"(c[0]), "+r"(c[1]), "+r"(c[2]), "+r"(c[3])
        : "r"(a[0]), "r"(a[1]), "r"(a[2]), "r"(a[3]), "r"(b[0]), "r"(b[1]));
}
__device__ __forceinline__ float qscale() {
    return 126.5f / __uint_as_float(g_maxabs);
}

// warp-collective exact dot: s = <x[ar], x[CNT+pr]>
__device__ __forceinline__ float exact_dot(const float* __restrict__ x,
                                           int ar, int pr, int lane) {
    const float4* ap = reinterpret_cast<const float4*>(x + (size_t)ar * KDIM);
    const float4* pp = reinterpret_cast<const float4*>(x + (size_t)(CNT + pr) * KDIM);
    float sum = 0.0f;
#pragma unroll
    for (int t = 0; t < 2; t++) {
        float4 a = ap[lane * 2 + t], p = pp[lane * 2 + t];
        sum += a.x * p.x + a.y * p.y + a.z * p.z + a.w * p.w;
    }
#pragma unroll
    for (int st = 16; st; st >>= 1) sum += __shfl_xor_sync(~0u, sum, st);
    return sum;
}

// ---------------- prep ----------------
__global__ void maxabs_kernel(const float* __restrict__ x) {
    __shared__ float red[8];
    const float4* X4 = reinterpret_cast<const float4*>(x);
    int i = blockIdx.x * 256 + threadIdx.x;
    float m = 0.0f;
#pragma unroll
    for (int t = 0; t < 4; t++) {
        float4 v = X4[i + t * 262144];
        m = fmaxf(m, fmaxf(fmaxf(fabsf(v.x), fabsf(v.y)), fmaxf(fabsf(v.z), fabsf(v.w))));
    }
#pragma unroll
    for (int st = 16; st; st >>= 1) m = fmaxf(m, __shfl_xor_sync(~0u, m, st));
    if ((threadIdx.x & 31) == 0) red[threadIdx.x >> 5] = m;
    __syncthreads();
    if (threadIdx.x < 8) {
        m = red[threadIdx.x];
#pragma unroll
        for (int st = 4; st; st >>= 1) m = fmaxf(m, __shfl_xor_sync(0xffu, m, st));
        if (threadIdx.x == 0) atomicMax(&g_maxabs, __float_as_uint(m));
    }
}

__global__ void quant_kernel(const float* __restrict__ x) {
    int i = blockIdx.x * 256 + threadIdx.x;
    float sc = qscale();
    float4 v = reinterpret_cast<const float4*>(x)[i];
    float q[4] = {v.x, v.y, v.z, v.w};
    uint32_t w = 0;
#pragma unroll
    for (int j = 0; j < 4; j++)
        w |= ((uint32_t)((int)rintf(q[j] * sc) & 0xff)) << (8 * j);
    reinterpret_cast<uint32_t*>(g_q)[i] = w;
}

// ---------------- screening GEMM ----------------
__global__ __launch_bounds__(256, 2)
void gemm_screen() {
    extern __shared__ char smem[];
    const uint32_t sb = smem_u32(smem);
    const int tid = threadIdx.x;
    const int w = tid >> 5, l = tid & 31;
    const int wm = w >> 2, wn = w & 3;
    const int bx = blockIdx.x, by = blockIdx.y;

    const char* Ag = (const char*)g_q + (size_t)(by * 128) * KDIM;
    const char* Bg = (const char*)g_q + (size_t)(CNT + bx * 128) * KDIM;

#pragma unroll
    for (int i = 0; i < 8; i++) {
        int idx = tid + i * 256;
        int row = idx >> 4, c16 = idx & 15;
        uint32_t so = (uint32_t)row * TSTRIDE + c16 * 16;
        cp_async16(sb + so, Ag + row * KDIM + c16 * 16);
        cp_async16(sb + TILE_BYTES + so, Bg + row * KDIM + c16 * 16);
    }
    asm volatile("cp.async.commit_group;" ::: "memory");
    asm volatile("cp.async.wait_group 0;" ::: "memory");
    __syncthreads();

    int acc[16][4];
#pragma unroll
    for (int t = 0; t < 16; t++)
#pragma unroll
        for (int e = 0; e < 4; e++) acc[t][e] = 0;

#pragma unroll
    for (int k0 = 0; k0 < KDIM; k0 += 32) {
        uint32_t a[4][4], b[4][2];
#pragma unroll
        for (int mt = 0; mt < 4; mt++) {
            const char* p = smem + (uint32_t)(wm * 64 + mt * 16 + (l >> 2)) * TSTRIDE
                          + k0 + (l & 3) * 4;
            a[mt][0] = *reinterpret_cast<const uint32_t*>(p);
            a[mt][1] = *reinterpret_cast<const uint32_t*>(p + 8 * TSTRIDE);
            a[mt][2] = *reinterpret_cast<const uint32_t*>(p + 16);
            a[mt][3] = *reinterpret_cast<const uint32_t*>(p + 8 * TSTRIDE + 16);
        }
#pragma unroll
        for (int nt = 0; nt < 4; nt++) {
            const char* p = smem + TILE_BYTES + (uint32_t)(wn * 32 + nt * 8 + (l >> 2)) * TSTRIDE
                          + k0 + (l & 3) * 4;
            b[nt][0] = *reinterpret_cast<const uint32_t*>(p);
            b[nt][1] = *reinterpret_cast<const uint32_t*>(p + 16);
        }
#pragma unroll
        for (int mt = 0; mt < 4; mt++)
#pragma unroll
            for (int nt = 0; nt < 4; nt++)
                mma_s8(acc[mt * 4 + nt], a[mt], b[nt]);
    }

    // ---- epilogue: group maxes (diag-excluded), staged in smem, coalesced dump ----
    const float inv2 = 1.0f / (qscale() * qscale());
    __syncthreads();               // mainloop smem reads done; reuse A region
    __nv_bfloat16* G1 = reinterpret_cast<__nv_bfloat16*>(smem);          // [128 rows][16 groups]
    __nv_bfloat16* G2 = reinterpret_cast<__nv_bfloat16*>(smem + 4096);   // [128 cols][16 groups]

#pragma unroll
    for (int mt = 0; mt < 4; mt++)
#pragma unroll
        for (int nt = 0; nt < 4; nt++)
#pragma unroll
            for (int h = 0; h < 2; h++) {
                int lr = wm * 64 + mt * 16 + (l >> 2) + h * 8;
                int lc = wn * 32 + nt * 8 + 2 * (l & 3);
                float s0 = (float)acc[mt * 4 + nt][2 * h + 0] * inv2;
                float s1 = (float)acc[mt * 4 + nt][2 * h + 1] * inv2;
                if (by * 128 + lr == bx * 128 + lc)     s0 = -2.0f;
                if (by * 128 + lr == bx * 128 + lc + 1) s1 = -2.0f;
                // row-direction group max over the 8 cols of slot nt
                float g = fmaxf(s0, s1);
                g = fmaxf(g, __shfl_xor_sync(0xffffffffu, g, 1));
                g = fmaxf(g, __shfl_xor_sync(0xffffffffu, g, 2));
                if ((l & 3) == 0) G1[lr * 16 + wn * 4 + nt] = __float2bfloat16_rn(g);
                // col-direction group max over the 8 rows of block (mt,h)
                float c0 = s0, c1 = s1;
                c0 = fmaxf(c0, __shfl_xor_sync(0xffffffffu, c0, 4));
                c0 = fmaxf(c0, __shfl_xor_sync(0xffffffffu, c0, 8));
                c0 = fmaxf(c0, __shfl_xor_sync(0xffffffffu, c0, 16));
                c1 = fmaxf(c1, __shfl_xor_sync(0xffffffffu, c1, 4));
                c1 = fmaxf(c1, __shfl_xor_sync(0xffffffffu, c1, 8));
                c1 = fmaxf(c1, __shfl_xor_sync(0xffffffffu, c1, 16));
                if (l < 4) {
                    int gidx = wm * 8 + mt * 2 + h;
                    G2[(wn * 32 + nt * 8 + 2 * l) * 16 + gidx]     = __float2bfloat16_rn(c0);
                    G2[(wn * 32 + nt * 8 + 2 * l + 1) * 16 + gidx] = __float2bfloat16_rn(c1);
                }
            }
    __syncthreads();

    // coalesced dump: 16 groups (32B) per row/col, 2 threads per row
    {
        int row = tid >> 1, half = tid & 1;
        uint4 v = *reinterpret_cast<const uint4*>(smem + row * 32 + half * 16);
        *reinterpret_cast<uint4*>(reinterpret_cast<char*>(g_grow)
            + ((size_t)(by * 128 + row) * 1024 + bx * 16 + half * 8) * 2) = v;
        uint4 w2 = *reinterpret_cast<const uint4*>(smem + 4096 + row * 32 + half * 16);
        *reinterpret_cast<uint4*>(reinterpret_cast<char*>(g_gcol)
            + ((size_t)(bx * 128 + row) * 1024 + by * 16 + half * 8) * 2) = w2;
    }
}

// ---------------- group-max scan + streaming exact fix ----------------
__global__ __launch_bounds__(256)
void scan4(const float* __restrict__ x) {
    const int warp = threadIdx.x >> 5, lane = threadIdx.x & 31;
    const int r = blockIdx.x * 8 + warp;       // row (dir 0) or col (dir 1)
    const int dir = blockIdx.y;

    const __nv_bfloat16* base = (dir ? g_gcol : g_grow) + (size_t)r * 1024;

    float vals[32];
    float lmax = -2.0f;
#pragma unroll
    for (int c = 0; c < 4; c++) {
        uint4 ch = *reinterpret_cast<const uint4*>(
            reinterpret_cast<const char*>(base) + c * 512 + lane * 16);
        unsigned u[4] = {ch.x, ch.y, ch.z, ch.w};
#pragma unroll
        for (int k = 0; k < 4; k++) {
            __nv_bfloat162 b2 = *reinterpret_cast<__nv_bfloat162*>(&u[k]);
            vals[c * 8 + 2 * k]     = __bfloat162float(b2.x);
            vals[c * 8 + 2 * k + 1] = __bfloat162float(b2.y);
            lmax = fmaxf(lmax, fmaxf(vals[c * 8 + 2 * k], vals[c * 8 + 2 * k + 1]));
        }
    }
#pragma unroll
    for (int st = 16; st; st >>= 1) lmax = fmaxf(lmax, __shfl_xor_sync(~0u, lmax, st));
    const float thr = lmax - MARGIN_C;

    float best = -2.0f;
#pragma unroll
    for (int c = 0; c < 4; c++) {
        unsigned m8 = 0;
#pragma unroll
        for (int k = 0; k < 8; k++)
            if (vals[c * 8 + k] >= thr) m8 |= 1u << k;
        unsigned bal = __ballot_sync(~0u, m8 != 0);
        while (bal) {
            int src = __ffs(bal) - 1; bal &= bal - 1;
            unsigned mm = __shfl_sync(~0u, m8, src);
            while (mm) {
                int bit = __ffs(mm) - 1; mm &= mm - 1;
                int j0 = (c * 256 + src * 8 + bit) * 8;   // first element of group
#pragma unroll
                for (int jj = 0; jj < 8; jj++) {
                    int j = j0 + jj;
                    if (j == r) continue;                  // uniform
                    float s = dir ? exact_dot(x, j, r, lane)
                                  : exact_dot(x, r, j, lane);
                    best = fmaxf(best, s);
                }
            }
        }
    }
    if (dir == 0) {
        float d = exact_dot(x, r, r, lane);
        if (lane == 0) { g_erow[r] = best; g_diag[r] = d; }
    } else if (lane == 0) {
        g_ecol[r] = best;
    }
}

__global__ void finish_kernel() {
    __shared__ float red[256];
    int i = blockIdx.x * 256 + threadIdx.x;
    float smax = fmaxf(g_erow[i], g_ecol[i]);
    float neg = sqrtf((1.0f - smax + EPSV) * 2.0f);
    float pos = sqrtf((1.0f - g_diag[i] + EPSV) * 2.0f);
    float t = fmaxf(1.0f - neg + pos, 0.0f);
    red[threadIdx.x] = t;
    __syncthreads();
#pragma unroll
    for (int s = 128; s > 0; s >>= 1) {
        if (threadIdx.x < s) red[threadIdx.x] += red[threadIdx.x + s];
        __syncthreads();
    }
    if (threadIdx.x == 0) g_partial[blockIdx.x] = red[0];
}

__global__ void final_kernel(float* __restrict__ out) {
    if (threadIdx.x == 0) {
        float s = 0.0f;
        for (int i = 0; i < CNT / 256; i++) s += g_partial[i];
        out[0] = s / (float)CNT;
    }
}

extern "C" void kernel_launch(void* const* d_in, const int* in_sizes, int n_in,
                              void* d_out, int out_size) {
    (void)in_sizes; (void)n_in; (void)out_size;
    const float* x = (const float*)d_in[0];
    float* out = (float*)d_out;

    cudaFuncSetAttribute((const void*)gemm_screen,
                         cudaFuncAttributeMaxDynamicSharedMemorySize, SM_TOTAL);

    maxabs_kernel<<<1024, 256>>>(x);
    quant_kernel<<<2 * CNT * KDIM / 4 / 256, 256>>>(x);
    dim3 grid(CNT / 128, CNT / 128);
    gemm_screen<<<grid, 256, SM_TOTAL>>>();
    dim3 sgrid(CNT / 8, 2);
    scan4<<<sgrid, 256>>>(x);
    finish_kernel<<<CNT / 256, 256>>>();
    final_kernel<<<1, 32>>>(out);
}

// round 13
// speedup vs baseline: 9.0964x; 1.1080x over previous
#include <cuda_runtime.h>
#include <cuda_bf16.h>
#include <cstdint>

// HardNetLoss, screen-then-fix v7:
//   int8 screening GEMM -> per-8-element group maxes (no S~ dump),
//   scan: group-max screen + per-LANE parallel exact fp32 dots via a
//   bounded drain-at-32 smem list (overflow impossible), diag fused.

#define CNT 8192
#define KDIM 256
#define EPSV 1e-6f
#define MARGIN_C 0.04f

#define TSTRIDE 272
#define TILE_BYTES (128 * TSTRIDE)        // 34816
#define SM_TOTAL (2 * TILE_BYTES + 1024)  // 70656

__device__ unsigned char g_q[2 * CNT * KDIM];
__device__ __nv_bfloat16 g_grow[(size_t)CNT * 1024];   // row-dir group maxes (16MB)
__device__ __nv_bfloat16 g_gcol[(size_t)CNT * 1024];   // col-dir group maxes (16MB)
__device__ float g_erow[CNT], g_ecol[CNT];
__device__ float g_diag[CNT];
__device__ float g_partial[CNT / 256];
__device__ unsigned g_maxabs;

__device__ __forceinline__ uint32_t smem_u32(const void* p) {
    uint32_t a;
    asm("{ .reg .u64 t; cvta.to.shared.u64 t, %1; cvt.u32.u64 %0, t; }" : "=r"(a) : "l"(p));
    return a;
}
__device__ __forceinline__ void cp_async16(uint32_t saddr, const void* gaddr) {
    asm volatile("cp.async.cg.shared.global [%0], [%1], 16;" :: "r"(saddr), "l"(gaddr) : "memory");
}
__device__ __forceinline__ void mma_s8(int* c, const uint32_t* a, const uint32_t* b) {
    asm volatile(
        "mma.sync.aligned.m16n8k32.row.col.s32.s8.s8.s32 "
        "{%0,%1,%2,%3}, {%4,%5,%6,%7}, {%8,%9}, {%0,%1,%2,%3};"
        : "+r"(c[0]), "+r"(c[1]), "+r"(c[2]), "+r"(c[3])
        : "r"(a[0]), "r"(a[1]), "r"(a[2]), "r"(a[3]), "r"(b[0]), "r"(b[1]));
}
__device__ __forceinline__ float qscale() {
    return 126.5f / __uint_as_float(g_maxabs);
}

// warp-collective exact dot (used once per warp for the diagonal)
__device__ __forceinline__ float exact_dot(const float* __restrict__ x,
                                           int ar, int pr, int lane) {
    const float4* ap = reinterpret_cast<const float4*>(x + (size_t)ar * KDIM);
    const float4* pp = reinterpret_cast<const float4*>(x + (size_t)(CNT + pr) * KDIM);
    float sum = 0.0f;
#pragma unroll
    for (int t = 0; t < 2; t++) {
        float4 a = ap[lane * 2 + t], p = pp[lane * 2 + t];
        sum += a.x * p.x + a.y * p.y + a.z * p.z + a.w * p.w;
    }
#pragma unroll
    for (int st = 16; st; st >>= 1) sum += __shfl_xor_sync(~0u, sum, st);
    return sum;
}

// thread-local exact dot (one candidate per lane)
__device__ __forceinline__ float thread_dot(const float* __restrict__ x,
                                            int ar, int pr) {
    const float4* ap = reinterpret_cast<const float4*>(x + (size_t)ar * KDIM);
    const float4* pp = reinterpret_cast<const float4*>(x + (size_t)(CNT + pr) * KDIM);
    float s0 = 0.0f, s1 = 0.0f;
#pragma unroll 8
    for (int i = 0; i < 64; i += 2) {
        float4 a = ap[i], p = pp[i];
        s0 += a.x * p.x + a.y * p.y + a.z * p.z + a.w * p.w;
        float4 a2 = ap[i + 1], p2 = pp[i + 1];
        s1 += a2.x * p2.x + a2.y * p2.y + a2.z * p2.z + a2.w * p2.w;
    }
    return s0 + s1;
}

// ---------------- prep ----------------
__global__ void maxabs_kernel(const float* __restrict__ x) {
    __shared__ float red[8];
    const float4* X4 = reinterpret_cast<const float4*>(x);
    int i = blockIdx.x * 256 + threadIdx.x;
    float m = 0.0f;
#pragma unroll
    for (int t = 0; t < 4; t++) {
        float4 v = X4[i + t * 262144];
        m = fmaxf(m, fmaxf(fmaxf(fabsf(v.x), fabsf(v.y)), fmaxf(fabsf(v.z), fabsf(v.w))));
    }
#pragma unroll
    for (int st = 16; st; st >>= 1) m = fmaxf(m, __shfl_xor_sync(~0u, m, st));
    if ((threadIdx.x & 31) == 0) red[threadIdx.x >> 5] = m;
    __syncthreads();
    if (threadIdx.x < 8) {
        m = red[threadIdx.x];
#pragma unroll
        for (int st = 4; st; st >>= 1) m = fmaxf(m, __shfl_xor_sync(0xffu, m, st));
        if (threadIdx.x == 0) atomicMax(&g_maxabs, __float_as_uint(m));
    }
}

__global__ void quant_kernel(const float* __restrict__ x) {
    int i = blockIdx.x * 256 + threadIdx.x;
    float sc = qscale();
    float4 v = reinterpret_cast<const float4*>(x)[i];
    float q[4] = {v.x, v.y, v.z, v.w};
    uint32_t w = 0;
#pragma unroll
    for (int j = 0; j < 4; j++)
        w |= ((uint32_t)((int)rintf(q[j] * sc) & 0xff)) << (8 * j);
    reinterpret_cast<uint32_t*>(g_q)[i] = w;
}

// ---------------- screening GEMM (unchanged from v6) ----------------
__global__ __launch_bounds__(256, 2)
void gemm_screen() {
    extern __shared__ char smem[];
    const uint32_t sb = smem_u32(smem);
    const int tid = threadIdx.x;
    const int w = tid >> 5, l = tid & 31;
    const int wm = w >> 2, wn = w & 3;
    const int bx = blockIdx.x, by = blockIdx.y;

    const char* Ag = (const char*)g_q + (size_t)(by * 128) * KDIM;
    const char* Bg = (const char*)g_q + (size_t)(CNT + bx * 128) * KDIM;

#pragma unroll
    for (int i = 0; i < 8; i++) {
        int idx = tid + i * 256;
        int row = idx >> 4, c16 = idx & 15;
        uint32_t so = (uint32_t)row * TSTRIDE + c16 * 16;
        cp_async16(sb + so, Ag + row * KDIM + c16 * 16);
        cp_async16(sb + TILE_BYTES + so, Bg + row * KDIM + c16 * 16);
    }
    asm volatile("cp.async.commit_group;" ::: "memory");
    asm volatile("cp.async.wait_group 0;" ::: "memory");
    __syncthreads();

    int acc[16][4];
#pragma unroll
    for (int t = 0; t < 16; t++)
#pragma unroll
        for (int e = 0; e < 4; e++) acc[t][e] = 0;

#pragma unroll
    for (int k0 = 0; k0 < KDIM; k0 += 32) {
        uint32_t a[4][4], b[4][2];
#pragma unroll
        for (int mt = 0; mt < 4; mt++) {
            const char* p = smem + (uint32_t)(wm * 64 + mt * 16 + (l >> 2)) * TSTRIDE
                          + k0 + (l & 3) * 4;
            a[mt][0] = *reinterpret_cast<const uint32_t*>(p);
            a[mt][1] = *reinterpret_cast<const uint32_t*>(p + 8 * TSTRIDE);
            a[mt][2] = *reinterpret_cast<const uint32_t*>(p + 16);
            a[mt][3] = *reinterpret_cast<const uint32_t*>(p + 8 * TSTRIDE + 16);
        }
#pragma unroll
        for (int nt = 0; nt < 4; nt++) {
            const char* p = smem + TILE_BYTES + (uint32_t)(wn * 32 + nt * 8 + (l >> 2)) * TSTRIDE
                          + k0 + (l & 3) * 4;
            b[nt][0] = *reinterpret_cast<const uint32_t*>(p);
            b[nt][1] = *reinterpret_cast<const uint32_t*>(p + 16);
        }
#pragma unroll
        for (int mt = 0; mt < 4; mt++)
#pragma unroll
            for (int nt = 0; nt < 4; nt++)
                mma_s8(acc[mt * 4 + nt], a[mt], b[nt]);
    }

    // ---- epilogue: group maxes (diag-excluded), staged in smem, coalesced dump ----
    const float inv2 = 1.0f / (qscale() * qscale());
    __syncthreads();
    __nv_bfloat16* G1 = reinterpret_cast<__nv_bfloat16*>(smem);
    __nv_bfloat16* G2 = reinterpret_cast<__nv_bfloat16*>(smem + 4096);

#pragma unroll
    for (int mt = 0; mt < 4; mt++)
#pragma unroll
        for (int nt = 0; nt < 4; nt++)
#pragma unroll
            for (int h = 0; h < 2; h++) {
                int lr = wm * 64 + mt * 16 + (l >> 2) + h * 8;
                int lc = wn * 32 + nt * 8 + 2 * (l & 3);
                float s0 = (float)acc[mt * 4 + nt][2 * h + 0] * inv2;
                float s1 = (float)acc[mt * 4 + nt][2 * h + 1] * inv2;
                if (by * 128 + lr == bx * 128 + lc)     s0 = -2.0f;
                if (by * 128 + lr == bx * 128 + lc + 1) s1 = -2.0f;
                float g = fmaxf(s0, s1);
                g = fmaxf(g, __shfl_xor_sync(0xffffffffu, g, 1));
                g = fmaxf(g, __shfl_xor_sync(0xffffffffu, g, 2));
                if ((l & 3) == 0) G1[lr * 16 + wn * 4 + nt] = __float2bfloat16_rn(g);
                float c0 = s0, c1 = s1;
                c0 = fmaxf(c0, __shfl_xor_sync(0xffffffffu, c0, 4));
                c0 = fmaxf(c0, __shfl_xor_sync(0xffffffffu, c0, 8));
                c0 = fmaxf(c0, __shfl_xor_sync(0xffffffffu, c0, 16));
                c1 = fmaxf(c1, __shfl_xor_sync(0xffffffffu, c1, 4));
                c1 = fmaxf(c1, __shfl_xor_sync(0xffffffffu, c1, 8));
                c1 = fmaxf(c1, __shfl_xor_sync(0xffffffffu, c1, 16));
                if (l < 4) {
                    int gidx = wm * 8 + mt * 2 + h;
                    G2[(wn * 32 + nt * 8 + 2 * l) * 16 + gidx]     = __float2bfloat16_rn(c0);
                    G2[(wn * 32 + nt * 8 + 2 * l + 1) * 16 + gidx] = __float2bfloat16_rn(c1);
                }
            }
    __syncthreads();

    {
        int row = tid >> 1, half = tid & 1;
        uint4 v = *reinterpret_cast<const uint4*>(smem + row * 32 + half * 16);
        *reinterpret_cast<uint4*>(reinterpret_cast<char*>(g_grow)
            + ((size_t)(by * 128 + row) * 1024 + bx * 16 + half * 8) * 2) = v;
        uint4 w2 = *reinterpret_cast<const uint4*>(smem + 4096 + row * 32 + half * 16);
        *reinterpret_cast<uint4*>(reinterpret_cast<char*>(g_gcol)
            + ((size_t)(bx * 128 + row) * 1024 + by * 16 + half * 8) * 2) = w2;
    }
}

// ---------------- group-max scan + lane-parallel exact fix ----------------
__global__ __launch_bounds__(256)
void scan5(const float* __restrict__ x) {
    __shared__ int lst[8][40];
    const int warp = threadIdx.x >> 5, lane = threadIdx.x & 31;
    const int r = blockIdx.x * 8 + warp;       // row (dir 0) or col (dir 1)
    const int dir = blockIdx.y;

    const __nv_bfloat16* base = (dir ? g_gcol : g_grow) + (size_t)r * 1024;

    float vals[32];
    float lmax = -2.0f;
#pragma unroll
    for (int c = 0; c < 4; c++) {
        uint4 ch = *reinterpret_cast<const uint4*>(
            reinterpret_cast<const char*>(base) + c * 512 + lane * 16);
        unsigned u[4] = {ch.x, ch.y, ch.z, ch.w};
#pragma unroll
        for (int k = 0; k < 4; k++) {
            __nv_bfloat162 b2 = *reinterpret_cast<__nv_bfloat162*>(&u[k]);
            vals[c * 8 + 2 * k]     = __bfloat162float(b2.x);
            vals[c * 8 + 2 * k + 1] = __bfloat162float(b2.y);
            lmax = fmaxf(lmax, fmaxf(vals[c * 8 + 2 * k], vals[c * 8 + 2 * k + 1]));
        }
    }
#pragma unroll
    for (int st = 16; st; st >>= 1) lmax = fmaxf(lmax, __shfl_xor_sync(~0u, lmax, st));
    const float thr = lmax - MARGIN_C;

    float best = -2.0f;
    int cnt = 0;   // warp-uniform

    // drain n entries of the warp list: one candidate per lane, parallel dots
    auto drain = [&](int n) {
        __syncwarp();
        int j = (lane < n) ? lst[warp][lane] : -1;
        float s = -2.0f;
        if (j >= 0 && j != r)
            s = dir ? thread_dot(x, j, r) : thread_dot(x, r, j);
        best = fmaxf(best, s);
        __syncwarp();
    };

#pragma unroll
    for (int c = 0; c < 4; c++) {
        unsigned m8 = 0;
#pragma unroll
        for (int k = 0; k < 8; k++)
            if (vals[c * 8 + k] >= thr) m8 |= 1u << k;
        unsigned bal = __ballot_sync(~0u, m8 != 0);
        while (bal) {
            int src = __ffs(bal) - 1; bal &= bal - 1;
            unsigned mm = __shfl_sync(~0u, m8, src);
            while (mm) {
                int bit = __ffs(mm) - 1; mm &= mm - 1;
                int j0 = (c * 256 + src * 8 + bit) * 8;   // first element of group
                __syncwarp();
                if (lane < 8) lst[warp][cnt + lane] = j0 + lane;
                cnt += 8;
                if (cnt >= 32) {
                    drain(32);
                    int rem = cnt - 32;
                    int tmp = (lane < rem) ? lst[warp][32 + lane] : 0;
                    __syncwarp();
                    if (lane < rem) lst[warp][lane] = tmp;
                    cnt = rem;
                }
            }
        }
    }
    if (cnt > 0) drain(cnt);

    // warp-reduce best
#pragma unroll
    for (int st = 16; st; st >>= 1) best = fmaxf(best, __shfl_xor_sync(~0u, best, st));

    if (dir == 0) {
        float d = exact_dot(x, r, r, lane);
        if (lane == 0) { g_erow[r] = best; g_diag[r] = d; }
    } else if (lane == 0) {
        g_ecol[r] = best;
    }
}

__global__ void finish_kernel() {
    __shared__ float red[256];
    int i = blockIdx.x * 256 + threadIdx.x;
    float smax = fmaxf(g_erow[i], g_ecol[i]);
    float neg = sqrtf((1.0f - smax + EPSV) * 2.0f);
    float pos = sqrtf((1.0f - g_diag[i] + EPSV) * 2.0f);
    float t = fmaxf(1.0f - neg + pos, 0.0f);
    red[threadIdx.x] = t;
    __syncthreads();
#pragma unroll
    for (int s = 128; s > 0; s >>= 1) {
        if (threadIdx.x < s) red[threadIdx.x] += red[threadIdx.x + s];
        __syncthreads();
    }
    if (threadIdx.x == 0) g_partial[blockIdx.x] = red[0];
}

__global__ void final_kernel(float* __restrict__ out) {
    if (threadIdx.x == 0) {
        float s = 0.0f;
        for (int i = 0; i < CNT / 256; i++) s += g_partial[i];
        out[0] = s / (float)CNT;
    }
}

extern "C" void kernel_launch(void* const* d_in, const int* in_sizes, int n_in,
                              void* d_out, int out_size) {
    (void)in_sizes; (void)n_in; (void)out_size;
    const float* x = (const float*)d_in[0];
    float* out = (float*)d_out;

    cudaFuncSetAttribute((const void*)gemm_screen,
                         cudaFuncAttributeMaxDynamicSharedMemorySize, SM_TOTAL);

    maxabs_kernel<<<1024, 256>>>(x);
    quant_kernel<<<2 * CNT * KDIM / 4 / 256, 256>>>(x);
    dim3 grid(CNT / 128, CNT / 128);
    gemm_screen<<<grid, 256, SM_TOTAL>>>();
    dim3 sgrid(CNT / 8, 2);
    scan5<<<sgrid, 256>>>(x);
    finish_kernel<<<CNT / 256, 256>>>();
    final_kernel<<<1, 32>>>(out);
}